// round 1
// baseline (speedup 1.0000x reference)
#include <cuda_runtime.h>

// SelfAttention_61804579389661 — GB300 sm_103a
//
// Algebraic simplification: softmax over a size-1 axis is identically 1.0,
// so attention == 1 and context[b,u] = sum_s hidden_states[b,s,u].
// All tanh/GEMM work in the reference is dead code w.r.t. the outputs.
//
// Output layout (out_size = 98304 fp32):
//   [0      .. 32767 ]  context   (B=32, U=1024)
//   [32768  .. 98303 ]  attention (B=32, S=2048, 1) == 1.0f

#define BB 32
#define SS 2048
#define UU 1024
#define NSPLIT 16
#define SCHUNK (SS / NSPLIT)   // 128 rows per split
#define U4 (UU / 4)            // 256 float4 per row

// Scratch: B * NSPLIT * U floats = 2 MiB (device global — no allocation).
__device__ float4 g_partial[BB * NSPLIT * U4];

__global__ void __launch_bounds__(256) partial_sum_kernel(const float4* __restrict__ hs) {
    const int b     = blockIdx.x;   // 0..31
    const int split = blockIdx.y;   // 0..15
    const int t     = threadIdx.x;  // 0..255 -> float4 lane within U

    // hidden_states[b, s, :] base for this split, as float4 rows of 256 elems
    const float4* __restrict__ row =
        hs + ((size_t)b * SS + (size_t)split * SCHUNK) * U4 + t;

    float4 acc = make_float4(0.f, 0.f, 0.f, 0.f);
#pragma unroll 8
    for (int s = 0; s < SCHUNK; ++s) {
        float4 v = row[(size_t)s * U4];
        acc.x += v.x; acc.y += v.y; acc.z += v.z; acc.w += v.w;
    }
    g_partial[(b * NSPLIT + split) * U4 + t] = acc;
}

__global__ void __launch_bounds__(256) finalize_kernel(float* __restrict__ out) {
    const int idx = blockIdx.x * blockDim.x + threadIdx.x;  // 0..98303
    if (idx < BB * UU) {
        const int b = idx >> 10;          // / 1024
        const int u = idx & (UU - 1);     // % 1024
        const float* __restrict__ p = (const float*)g_partial;
        float acc = 0.f;
#pragma unroll
        for (int k = 0; k < NSPLIT; ++k)
            acc += p[(size_t)(b * NSPLIT + k) * UU + u];
        out[idx] = acc;
    } else if (idx < BB * UU + BB * SS) {
        out[idx] = 1.0f;                  // softmax over size-1 axis
    }
}

extern "C" void kernel_launch(void* const* d_in, const int* in_sizes, int n_in,
                              void* d_out, int out_size) {
    // Inputs: [0]=s_prev, [1]=hidden_states, [2]=Ww, [3]=Wb, [4]=Uw, [5]=Ub,
    //         [6]=Vw, [7]=Vb. Only hidden_states is live.
    const float4* hs = (const float4*)d_in[1];
    float* out = (float*)d_out;

    dim3 gridA(BB, NSPLIT);
    partial_sum_kernel<<<gridA, 256>>>(hs);

    const int total = BB * UU + BB * SS;  // 98304
    finalize_kernel<<<(total + 255) / 256, 256>>>(out);
}

// round 3
// speedup vs baseline: 1.0424x; 1.0424x over previous
#include <cuda_runtime.h>

// SelfAttention_61804579389661 — GB300 sm_103a — Round 3
//
// Algebraic simplification: softmax over a size-1 axis is identically 1.0,
// so attention == 1 and context[b,u] = sum_s hidden_states[b,s,u].
//
// R3: single kernel, NO cross-block coordination. Each block owns a
// (batch, 64-wide U-chunk) and reduces over ALL of S; the 16 per-thread
// s-phase partials are combined in shared memory in fixed order
// (deterministic). Extra blocks write the all-ones attention region.
//
// Output layout (out_size = 98304 fp32):
//   [0      .. 32767 ]  context   (B=32, U=1024)
//   [32768  .. 98303 ]  attention (B=32, S=2048, 1) == 1.0f

#define BB 32
#define SS 2048
#define UU 1024
#define U4 (UU / 4)        // 256 float4 per row
#define NCHUNK 16          // U-chunks per batch row
#define C4 (U4 / NCHUNK)   // 16 float4 lanes per chunk
#define SPHASE 16          // s-strides per block (256 threads / 16 lanes)

__global__ void __launch_bounds__(256) fused_kernel(const float4* __restrict__ hs,
                                                    float* __restrict__ out) {
    const int b = blockIdx.x;   // 0..31
    const int y = blockIdx.y;   // 0..17
    const int t = threadIdx.x;  // 0..255

    if (y >= NCHUNK) {
        // ---- ones-writer blocks: attention region = 1.0 ----
        // 65536 floats = 16384 float4; 64 blocks (32 b x 2) x 256 threads.
        const int lb = b * 2 + (y - NCHUNK);            // 0..63
        float4* ones = (float4*)(out + BB * UU);
        ones[lb * 256 + t] = make_float4(1.f, 1.f, 1.f, 1.f);
        return;
    }

    // ---- block (b, y): sum hs[b, :, y*64 : y*64+64] over all S ----
    const int lane = t & (C4 - 1);      // 0..15  -> float4 column in chunk
    const int srow = t >> 4;            // 0..15  -> starting s, stride 16

    const float4* __restrict__ base =
        hs + ((size_t)b * SS + srow) * U4 + y * C4 + lane;

    float4 acc = make_float4(0.f, 0.f, 0.f, 0.f);
#pragma unroll 8
    for (int s = 0; s < SS / SPHASE; ++s) {             // 128 iters, stride 16 rows
        float4 v = base[(size_t)s * SPHASE * U4];
        acc.x += v.x; acc.y += v.y; acc.z += v.z; acc.w += v.w;
    }

    // ---- deterministic in-block reduction of the 16 s-phases ----
    __shared__ float4 smem[256];
    smem[t] = acc;
    __syncthreads();

    if (t < C4) {
        float4 r = make_float4(0.f, 0.f, 0.f, 0.f);
#pragma unroll
        for (int k = 0; k < SPHASE; ++k) {              // fixed order
            float4 v = smem[k * C4 + t];
            r.x += v.x; r.y += v.y; r.z += v.z; r.w += v.w;
        }
        ((float4*)out)[b * U4 + y * C4 + t] = r;
    }
}

extern "C" void kernel_launch(void* const* d_in, const int* in_sizes, int n_in,
                              void* d_out, int out_size) {
    // Inputs: [0]=s_prev, [1]=hidden_states, [2]=Ww, [3]=Wb, [4]=Uw, [5]=Ub,
    //         [6]=Vw, [7]=Vb. Only hidden_states is live.
    const float4* hs = (const float4*)d_in[1];
    float* out = (float*)d_out;

    dim3 grid(BB, NCHUNK + 2);
    fused_kernel<<<grid, 256>>>(hs, out);
}

// round 4
// speedup vs baseline: 1.0485x; 1.0059x over previous
#include <cuda_runtime.h>

// SelfAttention_61804579389661 — GB300 sm_103a — Round 4
//
// Algebraic simplification: softmax over a size-1 axis is identically 1.0,
// so attention == 1 and context[b,u] = sum_s hidden_states[b,s,u].
//
// R4: same zero-communication (batch, U-chunk) decomposition as R3, but
// 512 threads/block (16 warps) -> 8192 resident streaming warps (~84% of
// warp slots, single wave) for more memory-level parallelism, plus __ldcs
// (evict-first) on the read-once 256 MB stream.
//
// Output layout (out_size = 98304 fp32):
//   [0      .. 32767 ]  context   (B=32, U=1024)
//   [32768  .. 98303 ]  attention (B=32, S=2048, 1) == 1.0f

#define BB 32
#define SS 2048
#define UU 1024
#define U4 (UU / 4)        // 256 float4 per row
#define NCHUNK 16          // U-chunks per batch row
#define C4 (U4 / NCHUNK)   // 16 float4 lanes per chunk
#define NT 512             // threads per block
#define SPHASE (NT / C4)   // 32 s-strides per block

__global__ void __launch_bounds__(NT) fused_kernel(const float4* __restrict__ hs,
                                                   float* __restrict__ out) {
    const int b = blockIdx.x;   // 0..31
    const int y = blockIdx.y;   // 0..16
    const int t = threadIdx.x;  // 0..511

    if (y >= NCHUNK) {
        // ---- ones-writer blocks: attention region = 1.0 ----
        // 65536 floats = 16384 float4; 32 blocks x 512 threads.
        float4* ones = (float4*)(out + BB * UU);
        ones[b * NT + t] = make_float4(1.f, 1.f, 1.f, 1.f);
        return;
    }

    // ---- block (b, y): sum hs[b, :, y*64 : y*64+64] over all S ----
    const int lane = t & (C4 - 1);      // 0..15 -> float4 column in chunk
    const int srow = t >> 4;            // 0..31 -> starting s, stride 32

    const float4* __restrict__ base =
        hs + ((size_t)b * SS + srow) * U4 + y * C4 + lane;

    float4 acc = make_float4(0.f, 0.f, 0.f, 0.f);
#pragma unroll 8
    for (int s = 0; s < SS / SPHASE; ++s) {             // 64 iters, stride 32 rows
        float4 v = __ldcs(base + (size_t)s * SPHASE * U4);
        acc.x += v.x; acc.y += v.y; acc.z += v.z; acc.w += v.w;
    }

    // ---- deterministic in-block reduction of the 32 s-phases ----
    __shared__ float4 smem[NT];
    smem[t] = acc;
    __syncthreads();

    if (t < C4) {
        float4 r = make_float4(0.f, 0.f, 0.f, 0.f);
#pragma unroll
        for (int k = 0; k < SPHASE; ++k) {              // fixed order
            float4 v = smem[k * C4 + t];
            r.x += v.x; r.y += v.y; r.z += v.z; r.w += v.w;
        }
        ((float4*)out)[b * U4 + y * C4 + t] = r;
    }
}

extern "C" void kernel_launch(void* const* d_in, const int* in_sizes, int n_in,
                              void* d_out, int out_size) {
    // Inputs: [0]=s_prev, [1]=hidden_states, [2]=Ww, [3]=Wb, [4]=Uw, [5]=Ub,
    //         [6]=Vw, [7]=Vb. Only hidden_states is live.
    const float4* hs = (const float4*)d_in[1];
    float* out = (float*)d_out;

    dim3 grid(BB, NCHUNK + 1);
    fused_kernel<<<grid, NT>>>(hs, out);
}